// round 5
// baseline (speedup 1.0000x reference)
#include <cuda_runtime.h>
#include <cstdint>

#define MAXN 100000
#define FDIM 128
#define NGRAPH 64

// ---------------- scratch (device globals; referenced ONLY from device code) ---
__device__ float g_dinv[MAXN];                       // deg -> rsqrt(deg)
__device__ float g_xws [(size_t)MAXN * FDIM];        // (x @ W) * dinv[row]
__device__ float g_agg [(size_t)MAXN * FDIM];        // edge aggregation target
__device__ float g_h   [(size_t)MAXN * FDIM];        // layer activations
__device__ float g_sums[NGRAPH * FDIM];              // pooling sums
__device__ float g_cnts[NGRAPH];                     // pooling counts

// ---------------- degree / dinv ------------------------------------------------
__global__ void k_init_deg(int n) {
    int i = blockIdx.x * blockDim.x + threadIdx.x;
    if (i < n) g_dinv[i] = 1.0f;   // self-loop contributes 1
}

__global__ void k_deg_accum(const int* __restrict__ dst, int e, int n) {
    int i = blockIdx.x * blockDim.x + threadIdx.x;
    if (i >= e) return;
    int d = dst[i];
    if ((unsigned)d < (unsigned)n) atomicAdd(&g_dinv[d], 1.0f);
}

__global__ void k_finalize_dinv(int n) {
    int i = blockIdx.x * blockDim.x + threadIdx.x;
    if (i < n) g_dinv[i] = rsqrtf(g_dinv[i]);  // deg >= 1 always (self-loop)
}

// ---------------- fp32 SGEMM: out = (A[M,128] @ W[128,128]) * dinv[row] --------
// A == nullptr selects the internal activation buffer g_h as input.
// Writes the scaled result to BOTH g_xws and g_agg (agg init = self-loop msg).
// 128x128 block tile, BK=16, 256 threads, 8x8 per-thread microtile.
__global__ __launch_bounds__(256) void k_gemm_scale(
    const float* __restrict__ A_ext, const float* __restrict__ W, int M)
{
    __shared__ float As[16][128];   // [k][m] (transposed on store)
    __shared__ float Bs[16][128];   // [k][n]

    const float* A = (A_ext != nullptr) ? A_ext : (const float*)g_h;

    const int tid  = threadIdx.x;
    const int tr   = tid >> 4;      // 0..15
    const int tc   = tid & 15;      // 0..15
    const int row0 = blockIdx.x * 128;

    float acc[8][8];
#pragma unroll
    for (int i = 0; i < 8; i++)
#pragma unroll
        for (int j = 0; j < 8; j++) acc[i][j] = 0.0f;

    for (int k0 = 0; k0 < 128; k0 += 16) {
        // Load A tile: 128 rows x 16 k = 512 float4; 2 per thread. Transpose into As.
#pragma unroll
        for (int t = 0; t < 2; t++) {
            int f  = tid + t * 256;          // 0..511
            int r  = f >> 2;                 // row in tile
            int c4 = f & 3;                  // float4 index along k
            float4 v = make_float4(0.f, 0.f, 0.f, 0.f);
            int gr = row0 + r;
            if (gr < M)
                v = *reinterpret_cast<const float4*>(A + (size_t)gr * 128 + k0 + c4 * 4);
            As[c4 * 4 + 0][r] = v.x;
            As[c4 * 4 + 1][r] = v.y;
            As[c4 * 4 + 2][r] = v.z;
            As[c4 * 4 + 3][r] = v.w;
        }
        // Load B tile: 16 k x 128 n = 512 float4; direct layout.
#pragma unroll
        for (int t = 0; t < 2; t++) {
            int f  = tid + t * 256;
            int r  = f >> 5;                 // k row 0..15
            int c4 = f & 31;                 // float4 along n
            *reinterpret_cast<float4*>(&Bs[r][c4 * 4]) =
                *reinterpret_cast<const float4*>(W + (size_t)(k0 + r) * 128 + c4 * 4);
        }
        __syncthreads();

#pragma unroll
        for (int k = 0; k < 16; k++) {
            float a[8], b[8];
#pragma unroll
            for (int i = 0; i < 8; i++) a[i] = As[k][tr * 8 + i];
#pragma unroll
            for (int j = 0; j < 8; j++) b[j] = Bs[k][tc * 8 + j];
#pragma unroll
            for (int i = 0; i < 8; i++)
#pragma unroll
                for (int j = 0; j < 8; j++) acc[i][j] += a[i] * b[j];
        }
        __syncthreads();
    }

    // Epilogue: scale by dinv[row], write to xws and agg (agg = self-loop init).
#pragma unroll
    for (int i = 0; i < 8; i++) {
        int gr = row0 + tr * 8 + i;
        if (gr >= M) continue;
        float s = g_dinv[gr];
#pragma unroll
        for (int j4 = 0; j4 < 2; j4++) {
            float4 v;
            v.x = acc[i][j4 * 4 + 0] * s;
            v.y = acc[i][j4 * 4 + 1] * s;
            v.z = acc[i][j4 * 4 + 2] * s;
            v.w = acc[i][j4 * 4 + 3] * s;
            size_t off = (size_t)gr * 128 + tc * 8 + j4 * 4;
            *reinterpret_cast<float4*>(g_xws + off) = v;
            *reinterpret_cast<float4*>(g_agg + off) = v;
        }
    }
}

// ---------------- edge scatter: agg[dst] += xws[src] ---------------------------
// One warp per edge; each lane moves one float4 (32*16B = 512B = full row).
// Vector reduction: one REDG.128 per lane (4x fewer L2 atomic ops than scalar).
__global__ __launch_bounds__(256) void k_edge_agg(
    const int* __restrict__ src, const int* __restrict__ dst, int e, int n)
{
    int warp = (blockIdx.x * blockDim.x + threadIdx.x) >> 5;
    int lane = threadIdx.x & 31;
    if (warp >= e) return;
    int s = src[warp];
    int d = dst[warp];
    if ((unsigned)s >= (unsigned)n || (unsigned)d >= (unsigned)n) return;
    float4 v = *reinterpret_cast<const float4*>(g_xws + (size_t)s * 128 + lane * 4);
    float* p = g_agg + (size_t)d * 128 + lane * 4;
    asm volatile("red.global.add.v4.f32 [%0], {%1, %2, %3, %4};"
                 :: "l"(p), "f"(v.x), "f"(v.y), "f"(v.z), "f"(v.w) : "memory");
}

// ---------------- h = relu(agg * dinv[row] + b) --------------------------------
__global__ void k_bias_relu(const float* __restrict__ b, int n) {
    int idx = blockIdx.x * blockDim.x + threadIdx.x;   // one float4 per thread
    if (idx >= n * 32) return;
    int node = idx >> 5;
    int q    = idx & 31;
    float s  = g_dinv[node];
    float4 v = *reinterpret_cast<const float4*>(g_agg + (size_t)node * 128 + q * 4);
    float4 bb = *reinterpret_cast<const float4*>(b + q * 4);
    float4 r;
    r.x = fmaxf(fmaf(v.x, s, bb.x), 0.0f);
    r.y = fmaxf(fmaf(v.y, s, bb.y), 0.0f);
    r.z = fmaxf(fmaf(v.z, s, bb.z), 0.0f);
    r.w = fmaxf(fmaf(v.w, s, bb.w), 0.0f);
    *reinterpret_cast<float4*>(g_h + (size_t)node * 128 + q * 4) = r;
}

// ---------------- pooling -------------------------------------------------------
__global__ void k_pool_zero() {
    int i = blockIdx.x * blockDim.x + threadIdx.x;
    if (i < NGRAPH * FDIM) g_sums[i] = 0.0f;
    if (i < NGRAPH)        g_cnts[i] = 0.0f;
}

__global__ __launch_bounds__(256) void k_pool(const int* __restrict__ batch, int n) {
    int warp = (blockIdx.x * blockDim.x + threadIdx.x) >> 5;
    int lane = threadIdx.x & 31;
    if (warp >= n) return;
    int g = batch[warp];
    if ((unsigned)g >= (unsigned)NGRAPH) return;
    float4 v = *reinterpret_cast<const float4*>(g_h + (size_t)warp * 128 + lane * 4);
    float* p = g_sums + g * 128 + lane * 4;
    asm volatile("red.global.add.v4.f32 [%0], {%1, %2, %3, %4};"
                 :: "l"(p), "f"(v.x), "f"(v.y), "f"(v.z), "f"(v.w) : "memory");
    if (lane == 0) atomicAdd(&g_cnts[g], 1.0f);
}

// ---------------- final head: out[g,o] = (sums[g]/cnt[g]) @ Wlin + blin --------
__global__ void k_final(const float* __restrict__ Wlin, const float* __restrict__ blin,
                        float* __restrict__ out)
{
    int tid = threadIdx.x;
    if (tid >= NGRAPH * 10) return;
    int g = tid / 10;
    int o = tid % 10;
    float inv = 1.0f / fmaxf(g_cnts[g], 1.0f);
    float acc = 0.0f;
#pragma unroll 4
    for (int c = 0; c < 128; c++)
        acc += g_sums[g * 128 + c] * Wlin[c * 10 + o];
    out[tid] = acc * inv + blin[o];
}

// ---------------- launch --------------------------------------------------------
extern "C" void kernel_launch(void* const* d_in, const int* in_sizes, int n_in,
                              void* d_out, int out_size)
{
    const float* x     = (const float*)d_in[0];
    const int*   ei    = (const int*)d_in[1];    // int32! (JAX x64 disabled)
    const int*   batch = (const int*)d_in[2];    // int32!
    const float* W1    = (const float*)d_in[3];
    const float* b1    = (const float*)d_in[4];
    const float* W2    = (const float*)d_in[5];
    const float* b2    = (const float*)d_in[6];
    const float* Wlin  = (const float*)d_in[7];
    const float* blin  = (const float*)d_in[8];
    float*       out   = (float*)d_out;

    const int n = in_sizes[0] / FDIM;     // 100000
    const int e = in_sizes[1] / 2;        // 1600000
    const int* src = ei;
    const int* dst = ei + e;

    const int TB = 256;
    int nb_n    = (n + TB - 1) / TB;
    int nb_e    = (e + TB - 1) / TB;
    int nb_gemm = (n + 127) / 128;
    int nb_w    = ((n * 32) + TB - 1) / TB;               // one float4/thread over n*128
    int nb_ew   = (int)(((size_t)e * 32 + TB - 1) / TB);  // one warp/edge

    // degrees
    k_init_deg     <<<nb_n, TB>>>(n);
    k_deg_accum    <<<nb_e, TB>>>(dst, e, n);
    k_finalize_dinv<<<nb_n, TB>>>(n);

    // layer 1 (A = external x)
    k_gemm_scale<<<nb_gemm, TB>>>(x, W1, n);
    k_edge_agg  <<<nb_ew, TB>>>(src, dst, e, n);
    k_bias_relu <<<nb_w, TB>>>(b1, n);

    // layer 2 (A = nullptr -> internal g_h)
    k_gemm_scale<<<nb_gemm, TB>>>(nullptr, W2, n);
    k_edge_agg  <<<nb_ew, TB>>>(src, dst, e, n);
    k_bias_relu <<<nb_w, TB>>>(b2, n);

    // pooling + head
    k_pool_zero<<<(NGRAPH * FDIM + TB - 1) / TB, TB>>>();
    k_pool     <<<nb_w, TB>>>(batch, n);
    k_final    <<<1, 1024>>>(Wlin, blin, out);
}